// round 7
// baseline (speedup 1.0000x reference)
#include <cuda_runtime.h>

// ============================================================================
// EnasController R7: 512 threads, half-row-per-thread. ALL four LSTM weight
// matrices register-resident (128 regs/thread, no spills). No large smem
// matvecs in the main loop. 8 barrier phases/layer, deferred stats.
// ============================================================================

#define N_LAYERS 12
#define NB 6
#define HID 64

typedef unsigned long long u64;

// ---- shared memory layout (float offsets) ----
#define OF_WAT2  0                      // 64*80 (quarter-interleaved)
#define OF_WSOFT (OF_WAT2 + 64*80)      // 384
#define OF_VATTN (OF_WSOFT + 384)       // 64
#define OF_WEMB  (OF_VATTN + 64)        // 384
#define OF_GEMB  (OF_WEMB + 384)        // 64
#define OF_P     (OF_GEMB + 64)         // 7*256
#define OF_XS    (OF_P + 7*256)         // 64
#define OF_H0A   (OF_XS + 64)
#define OF_H0B   (OF_H0A + 64)
#define OF_H1A   (OF_H0B + 64)
#define OF_H1B   (OF_H1A + 64)
#define OF_ANCH  (OF_H1B + 64)          // 12*64
#define OF_AW1   (OF_ANCH + 12*64)      // 12*64
#define OF_W2OUT (OF_AW1 + 12*64)       // 64
#define OF_QVS   (OF_W2OUT + 64)        // 12*16
#define OF_LOGS  (OF_QVS + 192)         // 12*8
#define OF_GUMB  (OF_LOGS + 96)         // 72 -> 80
#define OF_GUMS  (OF_GUMB + 80)         // 132 -> 136
#define OF_BLP   (OF_GUMS + 136)        // 12
#define OF_BENT  (OF_BLP + 12)          // 12
#define OF_SLP   (OF_BENT + 12)         // 66 -> 68
#define OF_SENT  (OF_SLP + 68)          // 68
#define OF_SKL   (OF_SENT + 68)         // 68
#define OF_IREG  (OF_SKL + 68)          // 80 uints
#define IO_LKEY  0
#define IO_KB    24
#define IO_KS    48
#define SMEM_FLOATS (OF_IREG + 80)
#define SMEM_BYTES  (SMEM_FLOATS * 4)

#define FMA2(acc, w, x) \
    asm("fma.rn.f32x2 %0, %1, %2, %0;" : "+l"(acc) : "l"(w), "l"(x))

__device__ __forceinline__ float lo32(u64 v) { return __uint_as_float((unsigned)v); }
__device__ __forceinline__ float hi32(u64 v) { return __uint_as_float((unsigned)(v >> 32)); }

__device__ __forceinline__ unsigned rotl32(unsigned x, int r) {
    return (x << r) | (x >> (32 - r));
}

__device__ __forceinline__ void tf2x32(unsigned k0, unsigned k1,
                                       unsigned x0, unsigned x1,
                                       unsigned &o0, unsigned &o1) {
    const unsigned ks2 = k0 ^ k1 ^ 0x1BD11BDAu;
    x0 += k0; x1 += k1;
    x0+=x1; x1=rotl32(x1,13); x1^=x0;
    x0+=x1; x1=rotl32(x1,15); x1^=x0;
    x0+=x1; x1=rotl32(x1,26); x1^=x0;
    x0+=x1; x1=rotl32(x1, 6); x1^=x0;
    x0+=k1; x1+=ks2+1u;
    x0+=x1; x1=rotl32(x1,17); x1^=x0;
    x0+=x1; x1=rotl32(x1,29); x1^=x0;
    x0+=x1; x1=rotl32(x1,16); x1^=x0;
    x0+=x1; x1=rotl32(x1,24); x1^=x0;
    x0+=ks2; x1+=k0+2u;
    x0+=x1; x1=rotl32(x1,13); x1^=x0;
    x0+=x1; x1=rotl32(x1,15); x1^=x0;
    x0+=x1; x1=rotl32(x1,26); x1^=x0;
    x0+=x1; x1=rotl32(x1, 6); x1^=x0;
    x0+=k0; x1+=k1+3u;
    x0+=x1; x1=rotl32(x1,17); x1^=x0;
    x0+=x1; x1=rotl32(x1,29); x1^=x0;
    x0+=x1; x1=rotl32(x1,16); x1^=x0;
    x0+=x1; x1=rotl32(x1,24); x1^=x0;
    x0+=k1; x1+=ks2+4u;
    x0+=x1; x1=rotl32(x1,13); x1^=x0;
    x0+=x1; x1=rotl32(x1,15); x1^=x0;
    x0+=x1; x1=rotl32(x1,26); x1^=x0;
    x0+=x1; x1=rotl32(x1, 6); x1^=x0;
    x0+=ks2; x1+=k0+5u;
    o0 = x0; o1 = x1;
}

__device__ __forceinline__ unsigned rbits32(unsigned k0, unsigned k1, int idx) {
    unsigned o0, o1;
    tf2x32(k0, k1, 0u, (unsigned)idx, o0, o1);
    return o0 ^ o1;
}

__device__ __forceinline__ float gumbel_from_bits(unsigned bits) {
    const float TINY = 1.17549435e-38f;
    float f = __uint_as_float(0x3f800000u | (bits >> 9)) - 1.0f;
    float u = fmaxf(TINY, f + TINY);
    return -logf(-logf(u));
}

__device__ __forceinline__ float fsig(float x) {
    return __fdividef(1.0f, 1.0f + __expf(-x));
}
__device__ __forceinline__ float ftanh(float x) {
    float ax = fabsf(x);
    float e  = __expf(-2.0f * ax);
    float r  = __fdividef(1.0f - e, 1.0f + e);
    return copysignf(r, x);
}

// half-row (32 floats = 16 u64) dot with smem vector slice (8 ulonglong2)
__device__ __forceinline__ float dotr16(const u64* __restrict__ w,
                                        const ulonglong2* __restrict__ v) {
    u64 a0 = 0ull, a1 = 0ull, a2 = 0ull, a3 = 0ull;
#pragma unroll
    for (int k = 0; k < 8; k += 2) {
        ulonglong2 v0 = v[k], v1 = v[k + 1];
        FMA2(a0, w[2*k],     v0.x);
        FMA2(a1, w[2*k + 1], v0.y);
        FMA2(a2, w[2*k + 2], v1.x);
        FMA2(a3, w[2*k + 3], v1.y);
    }
    return ((lo32(a0) + hi32(a0)) + (lo32(a1) + hi32(a1)))
         + ((lo32(a2) + hi32(a2)) + (lo32(a3) + hi32(a3)));
}

// two fused half-row dots
__device__ __forceinline__ float dotr16x2(const u64* __restrict__ wa,
                                          const ulonglong2* __restrict__ va,
                                          const u64* __restrict__ wb,
                                          const ulonglong2* __restrict__ vb) {
    u64 a0 = 0ull, a1 = 0ull, a2 = 0ull, a3 = 0ull;
    u64 b0 = 0ull, b1 = 0ull, b2 = 0ull, b3 = 0ull;
#pragma unroll
    for (int k = 0; k < 8; k += 2) {
        ulonglong2 v0 = va[k], v1 = va[k + 1];
        FMA2(a0, wa[2*k],     v0.x);
        FMA2(a1, wa[2*k + 1], v0.y);
        FMA2(a2, wa[2*k + 2], v1.x);
        FMA2(a3, wa[2*k + 3], v1.y);
        ulonglong2 u0 = vb[k], u1 = vb[k + 1];
        FMA2(b0, wb[2*k],     u0.x);
        FMA2(b1, wb[2*k + 1], u0.y);
        FMA2(b2, wb[2*k + 2], u1.x);
        FMA2(b3, wb[2*k + 3], u1.y);
    }
    float sa = ((lo32(a0) + hi32(a0)) + (lo32(a1) + hi32(a1)))
             + ((lo32(a2) + hi32(a2)) + (lo32(a3) + hi32(a3)));
    float sb = ((lo32(b0) + hi32(b0)) + (lo32(b1) + hi32(b1)))
             + ((lo32(b2) + hi32(b2)) + (lo32(b3) + hi32(b3)));
    return sa + sb;
}

// Epilogue for 512-thread layout. lane l = r4*8 + gate*2 + half.
// preHalf: this thread's half-row partial. addAfter: bias or P (added once).
__device__ __forceinline__ void epi(float preHalf, float addAfter, float& c,
                                    float* __restrict__ hout,
                                    int l, int row, int gate) {
    float acc = preHalf + __shfl_xor_sync(0xffffffffu, preHalf, 1);
    acc += addAfter;
    float act = (gate == 2) ? ftanh(acc) : fsig(acc);
    int base = l & 24;   // r4*8
    float ai = __shfl_sync(0xffffffffu, act, base + 0);
    float af = __shfl_sync(0xffffffffu, act, base + 2);
    float ag = __shfl_sync(0xffffffffu, act, base + 4);
    float ao = __shfl_sync(0xffffffffu, act, base + 6);
    float cn = af * c + ai * ag;
    c = cn;
    float hv = ao * ftanh(cn);
    if ((l & 7) == 0) hout[row] = hv;
    __syncthreads();
}

__global__ __launch_bounds__(512, 1)
void enas_controller_kernel(const float* __restrict__ g_emb,
                            const float* __restrict__ w_emb,
                            const float* __restrict__ w_soft,
                            const float* __restrict__ w_attn2,
                            const float* __restrict__ v_attn,
                            const float* __restrict__ w_ih0,
                            const float* __restrict__ w_hh0,
                            const float* __restrict__ b_ih0,
                            const float* __restrict__ b_hh0,
                            const float* __restrict__ w_ih1,
                            const float* __restrict__ w_hh1,
                            const float* __restrict__ b_ih1,
                            const float* __restrict__ b_hh1,
                            const int* __restrict__ seed_p,
                            float* __restrict__ out3) {
    extern __shared__ __align__(16) float S[];
    unsigned* SI = (unsigned*)&S[OF_IREG];
    const int t = threadIdx.x;
    const int w = t >> 5, l = t & 31;
    const int half = l & 1;
    const int gate = (l >> 1) & 3;
    const int r4   = l >> 3;
    const int row  = w * 4 + r4;          // 0..63
    const int R    = gate * 64 + row;     // gate row 0..255
    const int half4 = half * 4;           // ulonglong2 offset into 64-float vecs

    // ---- stage small smem tables ----
    {
        // wat2: quarter-interleaved, row stride 80 floats, quarter q at q*20
        for (int idx = t; idx < 64 * 64; idx += 512) {
            int r = idx >> 6, j = idx & 63;
            S[OF_WAT2 + r*80 + (j >> 4)*20 + (j & 15)] = __ldg(&w_attn2[r*64 + j]);
        }
        if (t < NB*16) *(float4*)&S[OF_WSOFT + t*4] = __ldg(&((const float4*)w_soft)[t]);
        if (t >= 128 && t < 128 + NB*16)
            *(float4*)&S[OF_WEMB + (t-128)*4] = __ldg(&((const float4*)w_emb)[t-128]);
        if (t >= 256 && t < 272)
            *(float4*)&S[OF_GEMB + (t-256)*4] = __ldg(&((const float4*)g_emb)[t-256]);
        if (t >= 288 && t < 288 + HID) {
            S[OF_VATTN + t - 288] = __ldg(&v_attn[t - 288]);
            S[OF_H0A + t - 288] = 0.f;
            S[OF_H1A + t - 288] = 0.f;
        }
    }

    // ---- register weights: four half-rows (16 u64 each) ----
    u64 wi0[16], wh0[16], wi1[16], wh1[16];
    {
        const ulonglong2* p0 = (const ulonglong2*)(w_ih0 + R*HID + half*32);
        const ulonglong2* p1 = (const ulonglong2*)(w_hh0 + R*HID + half*32);
        const ulonglong2* p2 = (const ulonglong2*)(w_ih1 + R*HID + half*32);
        const ulonglong2* p3 = (const ulonglong2*)(w_hh1 + R*HID + half*32);
#pragma unroll
        for (int k = 0; k < 8; k++) {
            ulonglong2 v0 = __ldg(&p0[k]);
            ulonglong2 v1 = __ldg(&p1[k]);
            ulonglong2 v2 = __ldg(&p2[k]);
            ulonglong2 v3 = __ldg(&p3[k]);
            wi0[2*k] = v0.x; wi0[2*k + 1] = v0.y;
            wh0[2*k] = v1.x; wh0[2*k + 1] = v1.y;
            wi1[2*k] = v2.x; wi1[2*k + 1] = v2.y;
            wh1[2*k] = v3.x; wh1[2*k + 1] = v3.y;
        }
    }
    const float b0R = __ldg(&b_ih0[R]) + __ldg(&b_hh0[R]);
    const float b1R = __ldg(&b_ih1[R]) + __ldg(&b_hh1[R]);

    // ---- RNG: serial key chain ----
    if (t == 0) {
        unsigned k0 = 0u, k1 = (unsigned)seed_p[0];
        for (int lid = 0; lid < N_LAYERS; lid++) {
            SI[IO_LKEY + 2*lid]     = k0;
            SI[IO_LKEY + 2*lid + 1] = k1;
            unsigned a0, a1;
            tf2x32(k0, k1, 0u, 0u, a0, a1);
            k0 = a0; k1 = a1;
        }
    }
    __syncthreads();

    // subkeys + P table
    if (t < 24) {
        int lid = t >> 1, which = t & 1;
        unsigned o0, o1;
        tf2x32(SI[IO_LKEY + 2*lid], SI[IO_LKEY + 2*lid + 1], 0u, (unsigned)(1 + which), o0, o1);
        int base = which ? IO_KS : IO_KB;
        SI[base + 2*lid] = o0; SI[base + 2*lid + 1] = o1;
    }
    {
#pragma unroll
        for (int b = 0; b < 7; b++) {
            const ulonglong2* vec = (const ulonglong2*)
                ((b < 6) ? &S[OF_WEMB + b*HID] : &S[OF_GEMB]);
            float ph = dotr16(wi0, vec + half4);
            float s = ph + __shfl_xor_sync(0xffffffffu, ph, 1);
            if (half == 0) S[OF_P + b*256 + R] = b0R + s;
        }
    }
    __syncthreads();

    // gumbels
    if (t < 72) {
        int lid = t / NB, j = t % NB;
        S[OF_GUMB + lid*NB + j] =
            gumbel_from_bits(rbits32(SI[IO_KB + 2*lid], SI[IO_KB + 2*lid + 1], j));
    } else if (t < 72 + 132) {
        int f = t - 72;
        int lid = 1;
        while (f >= lid*(lid+1)) lid++;
        int j = f - lid*(lid-1);
        S[OF_GUMS + f] =
            gumbel_from_bits(rbits32(SI[IO_KS + 2*lid], SI[IO_KS + 2*lid + 1], j));
    }
    __syncthreads();

    float c0 = 0.f, c1 = 0.f;

#pragma unroll 1
    for (int lid = 0; lid < N_LAYERS; ++lid) {
        // ===== phase 1: call1-cell0 (reads H0A, writes H0B) =====
        if (lid < 2) {
            float pre = dotr16(wh0, (const ulonglong2*)&S[OF_H0A] + half4);
            epi(pre, S[OF_P + 6*256 + R], c0, &S[OF_H0B], l, row, gate);
        } else {
            float pre = dotr16x2(wi0, (const ulonglong2*)&S[OF_XS] + half4,
                                 wh0, (const ulonglong2*)&S[OF_H0A] + half4);
            epi(pre, b0R, c0, &S[OF_H0B], l, row, gate);
        }
        // ===== phase 2: call1-cell1 =====
        {
            float pre = dotr16x2(wi1, (const ulonglong2*)&S[OF_H0B] + half4,
                                 wh1, (const ulonglong2*)&S[OF_H1A] + half4);
            epi(pre, b1R, c1, &S[OF_H1B], l, row, gate);
        }
        // ===== phase 3: logits = w_soft @ H1B (2 full warps) =====
        if (t < 64) {
            int j = t >> 3, k0 = t & 7;
            int jc = (j < NB) ? j : 0;
            const float4* wv = (const float4*)&S[OF_WSOFT + jc*HID + k0*8];
            const float4* hv = (const float4*)&S[OF_H1B + k0*8];
            float4 wa = wv[0], wb = wv[1];
            float4 ha = hv[0], hb = hv[1];
            float s = wa.x*ha.x + wa.y*ha.y + wa.z*ha.z + wa.w*ha.w
                    + wb.x*hb.x + wb.y*hb.y + wb.z*hb.z + wb.w*hb.w;
            s += __shfl_down_sync(0xffffffffu, s, 4, 8);
            s += __shfl_down_sync(0xffffffffu, s, 2, 8);
            s += __shfl_down_sync(0xffffffffu, s, 1, 8);
            if (k0 == 0 && j < NB) S[OF_LOGS + lid*8 + j] = s;
        }
        __syncthreads();

        // ===== phase 4: call2-cell0 (redundant argmax; P[best]) =====
        {
            float bz = S[OF_LOGS + lid*8] + S[OF_GUMB + lid*NB];
            int best = 0;
#pragma unroll
            for (int j = 1; j < NB; j++) {
                float z = S[OF_LOGS + lid*8 + j] + S[OF_GUMB + lid*NB + j];
                if (z > bz) { bz = z; best = j; }
            }
            float pre = dotr16(wh0, (const ulonglong2*)&S[OF_H0B] + half4);
            epi(pre, S[OF_P + best*256 + R], c0, &S[OF_H0A], l, row, gate);
        }
        // ===== phase 5: call2-cell1 =====
        {
            float pre = dotr16x2(wi1, (const ulonglong2*)&S[OF_H0A] + half4,
                                 wh1, (const ulonglong2*)&S[OF_H1B] + half4);
            epi(pre, b1R, c1, &S[OF_H1A], l, row, gate);
        }
        // ===== phase 6: anchor. warps 0-7: w2out (4 thr/row); warps 8-9: anchors =====
        if (t < 256) {
            int r = t >> 2, q = t & 3;
            const ulonglong2* wv = (const ulonglong2*)&S[OF_WAT2 + r*80 + q*20];
            const ulonglong2* hv = (const ulonglong2*)&S[OF_H1A + q*16];
            u64 a0 = 0ull, a1 = 0ull;
            ulonglong2 w0 = wv[0], h0 = hv[0];
            ulonglong2 w1 = wv[1], h1 = hv[1];
            ulonglong2 w2 = wv[2], h2 = hv[2];
            ulonglong2 w3 = wv[3], h3 = hv[3];
            FMA2(a0, w0.x, h0.x); FMA2(a1, w0.y, h0.y);
            FMA2(a0, w1.x, h1.x); FMA2(a1, w1.y, h1.y);
            FMA2(a0, w2.x, h2.x); FMA2(a1, w2.y, h2.y);
            FMA2(a0, w3.x, h3.x); FMA2(a1, w3.y, h3.y);
            float s = (lo32(a0) + hi32(a0)) + (lo32(a1) + hi32(a1));
            s += __shfl_down_sync(0xffffffffu, s, 2, 4);
            s += __shfl_down_sync(0xffffffffu, s, 1, 4);
            if (q == 0) {
                S[OF_W2OUT + r] = s;
                S[OF_AW1 + lid*HID + r] = s;
            }
        } else if (t < 320) {
            int j = t - 256;
            S[OF_ANCH + lid*HID + j] = S[OF_H1A + j];
        }
        __syncthreads();

        if (lid > 0) {
            // ===== phase 7: attention q (16 thr/row; warps 0-5 full) =====
            if (t < 192) {
                int r = t >> 4, k0 = t & 15;
                int rc = (r < lid) ? r : 0;
                float s = 0.f;
#pragma unroll
                for (int k = 0; k < 4; k++) {
                    int j = k0 + 16*k;
                    s += ftanh(S[OF_AW1 + rc*HID + j] + S[OF_W2OUT + j]) * S[OF_VATTN + j];
                }
                s += __shfl_down_sync(0xffffffffu, s, 8, 16);
                s += __shfl_down_sync(0xffffffffu, s, 4, 16);
                s += __shfl_down_sync(0xffffffffu, s, 2, 16);
                s += __shfl_down_sync(0xffffffffu, s, 1, 16);
                if (k0 == 0 && r < lid) S[OF_QVS + lid*16 + r] = s;
            }
            __syncthreads();

            // ===== phase 8: xs (redundant skip decisions + anchor average) =====
            if (t < HID) {
                int sc = 0;
                float acc = 0.f;
                for (int i = 0; i < lid; i++) {
                    float l0 = 1.5f * ftanh(S[OF_QVS + lid*16 + i]);
                    float g0 = S[OF_GUMS + lid*(lid-1) + 2*i];
                    float g1 = S[OF_GUMS + lid*(lid-1) + 2*i + 1];
                    int sk = ((-l0) + g1 > l0 + g0) ? 1 : 0;
                    sc += sk;
                    acc += sk ? S[OF_ANCH + i*HID + t] : 0.0f;
                }
                S[OF_XS + t] = __fdividef(acc, 1.0f + (float)sc);
            }
            __syncthreads();
        }
    }

    // ===== deferred stats (once) =====
    if (t < 12) {
        float lv[NB];
#pragma unroll
        for (int j = 0; j < NB; j++) lv[j] = S[OF_LOGS + t*8 + j];
        float m = lv[0];
#pragma unroll
        for (int j = 1; j < NB; j++) m = fmaxf(m, lv[j]);
        float s = 0.f;
#pragma unroll
        for (int j = 0; j < NB; j++) s += __expf(lv[j] - m);
        float lse = __logf(s);
        int best = 0;
        float bz = lv[0] + S[OF_GUMB + t*NB];
#pragma unroll
        for (int j = 1; j < NB; j++) {
            float z = lv[j] + S[OF_GUMB + t*NB + j];
            if (z > bz) { bz = z; best = j; }
        }
        S[OF_BLP + t] = (lv[best] - m) - lse;
        float ent = 0.f;
#pragma unroll
        for (int j = 0; j < NB; j++) {
            float lp = (lv[j] - m) - lse;
            ent -= __expf(lp) * lp;
        }
        S[OF_BENT + t] = ent;
    } else if (t >= 64 && t < 64 + 66) {
        int f = t - 64;
        int lid = 1;
        while (f >= (lid*(lid+1)) >> 1) lid++;
        int r = f - ((lid*(lid-1)) >> 1);
        float q = S[OF_QVS + lid*16 + r];
        float l0 = 1.5f * ftanh(q);
        float l1 = -l0;
        float g0 = S[OF_GUMS + lid*(lid-1) + 2*r];
        float g1 = S[OF_GUMS + lid*(lid-1) + 2*r + 1];
        float m = fmaxf(l0, l1);
        float lsr = __logf(__expf(l0 - m) + __expf(l1 - m));
        float lp0 = (l0 - m) - lsr;
        float lp1 = (l1 - m) - lsr;
        S[OF_SLP + f]  = (l1 + g1 > l0 + g0) ? lp1 : lp0;
        S[OF_SENT + f] = -(__expf(lp0)*lp0 + __expf(lp1)*lp1);
        float s0 = __fdividef(1.0f, 1.0f + __expf(-l0));
        float s1 = __fdividef(1.0f, 1.0f + __expf(-l1));
        S[OF_SKL + f] = s0 * __logf(__fdividef(s0, 0.8f))
                      + s1 * __logf(__fdividef(s1, 0.8f));
    }
    __syncthreads();

    if (t < 32) {
        float s1 = 0.f, s2 = 0.f, s3 = 0.f;
        for (int i = t; i < 12; i += 32) { s1 += S[OF_BLP + i]; s2 += S[OF_BENT + i]; }
        for (int i = t; i < 66; i += 32) {
            s1 += S[OF_SLP + i]; s2 += S[OF_SENT + i]; s3 += S[OF_SKL + i];
        }
#pragma unroll
        for (int off = 16; off > 0; off >>= 1) {
            s1 += __shfl_down_sync(0xffffffffu, s1, off);
            s2 += __shfl_down_sync(0xffffffffu, s2, off);
            s3 += __shfl_down_sync(0xffffffffu, s3, off);
        }
        if (t == 0) {
            out3[0] = s1;
            out3[1] = s2;
            out3[2] = s3;
        }
    }
}

extern "C" void kernel_launch(void* const* d_in, const int* in_sizes, int n_in,
                              void* d_out, int out_size) {
    const float* g_emb   = (const float*)d_in[0];
    const float* w_emb   = (const float*)d_in[1];
    const float* w_soft  = (const float*)d_in[2];
    const float* w_attn2 = (const float*)d_in[3];
    const float* v_attn  = (const float*)d_in[4];
    const float* w_ih0   = (const float*)d_in[5];
    const float* w_hh0   = (const float*)d_in[6];
    const float* b_ih0   = (const float*)d_in[7];
    const float* b_hh0   = (const float*)d_in[8];
    const float* w_ih1   = (const float*)d_in[9];
    const float* w_hh1   = (const float*)d_in[10];
    const float* b_ih1   = (const float*)d_in[11];
    const float* b_hh1   = (const float*)d_in[12];
    const int*   seed    = (const int*)d_in[13];

    cudaFuncSetAttribute(enas_controller_kernel,
                         cudaFuncAttributeMaxDynamicSharedMemorySize, SMEM_BYTES);
    enas_controller_kernel<<<1, 512, SMEM_BYTES>>>(
        g_emb, w_emb, w_soft, w_attn2, v_attn,
        w_ih0, w_hh0, b_ih0, b_hh0,
        w_ih1, w_hh1, b_ih1, b_hh1,
        seed, (float*)d_out);
}

// round 8
// speedup vs baseline: 1.3326x; 1.3326x over previous
#include <cuda_runtime.h>

// ============================================================================
// EnasController R8: R6 base (best: 55.5us, rel_err 0.0) with bitwise-safe
// latency cuts: wh1-dot hoisted one phase earlier, logits fused into phase 4
// (overlapped with dots), skip decisions hoisted into phase 7.
// 256 threads, wh0/wh1/wi1 register-resident.
// ============================================================================

#define N_LAYERS 12
#define NB 6
#define HID 64
#define PAD 68

typedef unsigned long long u64;

// ---- shared memory layout (float offsets) ----
#define OF_WI0   0                        // 256*68
#define OF_WAT2  (OF_WI0 + 256*PAD)       // 64*68
#define OF_WSOFT (OF_WAT2 + 64*PAD)       // 6*64
#define OF_VATTN (OF_WSOFT + NB*HID)      // 64
#define OF_WEMB  (OF_VATTN + 64)          // 6*64
#define OF_GEMB  (OF_WEMB + NB*HID)       // 64
#define OF_P     (OF_GEMB + 64)           // 7*256
#define OF_XS    (OF_P + 7*256)           // 64
#define OF_H0A   (OF_XS + 64)
#define OF_H0B   (OF_H0A + 64)
#define OF_H1A   (OF_H0B + 64)
#define OF_H1B   (OF_H1A + 64)
#define OF_ANCH  (OF_H1B + 64)            // 12*64
#define OF_AW1   (OF_ANCH + 12*64)        // 12*64
#define OF_W2OUT (OF_AW1 + 12*64)         // 64
#define OF_QVS   (OF_W2OUT + 64)          // 12*16
#define OF_LOGS  (OF_QVS + 12*16)         // 12*8
#define OF_GUMB  (OF_LOGS + 12*8)         // 72
#define OF_GUMS  (OF_GUMB + 72)           // 132
#define OF_BLP   (OF_GUMS + 132)          // 12
#define OF_BENT  (OF_BLP + 12)            // 12
#define OF_SLP   (OF_BENT + 12)           // 66
#define OF_SENT  (OF_SLP + 66)            // 66
#define OF_SKL   (OF_SENT + 66)           // 66
#define OF_SKF   (OF_SKL + 66 + 2)        // 16 skip flags (0/1 floats)
#define OF_IREG  (OF_SKF + 16)            // uint keys region
#define IO_LKEY  0
#define IO_KB    24
#define IO_KS    48
#define SMEM_FLOATS (OF_IREG + 80)
#define SMEM_BYTES  (SMEM_FLOATS * 4)

#define FMA2(acc, w, x) \
    asm("fma.rn.f32x2 %0, %1, %2, %0;" : "+l"(acc) : "l"(w), "l"(x))

__device__ __forceinline__ float lo32(u64 v) { return __uint_as_float((unsigned)v); }
__device__ __forceinline__ float hi32(u64 v) { return __uint_as_float((unsigned)(v >> 32)); }

__device__ __forceinline__ unsigned rotl32(unsigned x, int r) {
    return (x << r) | (x >> (32 - r));
}

__device__ __forceinline__ void tf2x32(unsigned k0, unsigned k1,
                                       unsigned x0, unsigned x1,
                                       unsigned &o0, unsigned &o1) {
    const unsigned ks2 = k0 ^ k1 ^ 0x1BD11BDAu;
    x0 += k0; x1 += k1;
    x0+=x1; x1=rotl32(x1,13); x1^=x0;
    x0+=x1; x1=rotl32(x1,15); x1^=x0;
    x0+=x1; x1=rotl32(x1,26); x1^=x0;
    x0+=x1; x1=rotl32(x1, 6); x1^=x0;
    x0+=k1; x1+=ks2+1u;
    x0+=x1; x1=rotl32(x1,17); x1^=x0;
    x0+=x1; x1=rotl32(x1,29); x1^=x0;
    x0+=x1; x1=rotl32(x1,16); x1^=x0;
    x0+=x1; x1=rotl32(x1,24); x1^=x0;
    x0+=ks2; x1+=k0+2u;
    x0+=x1; x1=rotl32(x1,13); x1^=x0;
    x0+=x1; x1=rotl32(x1,15); x1^=x0;
    x0+=x1; x1=rotl32(x1,26); x1^=x0;
    x0+=x1; x1=rotl32(x1, 6); x1^=x0;
    x0+=k0; x1+=k1+3u;
    x0+=x1; x1=rotl32(x1,17); x1^=x0;
    x0+=x1; x1=rotl32(x1,29); x1^=x0;
    x0+=x1; x1=rotl32(x1,16); x1^=x0;
    x0+=x1; x1=rotl32(x1,24); x1^=x0;
    x0+=k1; x1+=ks2+4u;
    x0+=x1; x1=rotl32(x1,13); x1^=x0;
    x0+=x1; x1=rotl32(x1,15); x1^=x0;
    x0+=x1; x1=rotl32(x1,26); x1^=x0;
    x0+=x1; x1=rotl32(x1, 6); x1^=x0;
    x0+=ks2; x1+=k0+5u;
    o0 = x0; o1 = x1;
}

__device__ __forceinline__ unsigned rbits32(unsigned k0, unsigned k1, int idx) {
    unsigned o0, o1;
    tf2x32(k0, k1, 0u, (unsigned)idx, o0, o1);
    return o0 ^ o1;
}

__device__ __forceinline__ float gumbel_from_bits(unsigned bits) {
    const float TINY = 1.17549435e-38f;
    float f = __uint_as_float(0x3f800000u | (bits >> 9)) - 1.0f;
    float u = fmaxf(TINY, f + TINY);
    return -logf(-logf(u));
}

__device__ __forceinline__ float fsig(float x) {
    return __fdividef(1.0f, 1.0f + __expf(-x));
}
__device__ __forceinline__ float ftanh(float x) {
    float ax = fabsf(x);
    float e  = __expf(-2.0f * ax);
    float r  = __fdividef(1.0f - e, 1.0f + e);
    return copysignf(r, x);
}

// dot of padded smem row with smem vector (packed f32x2)
__device__ __forceinline__ float dot64p(const ulonglong2* __restrict__ w,
                                        const ulonglong2* __restrict__ v) {
    u64 a0 = 0ull, a1 = 0ull, a2 = 0ull, a3 = 0ull;
#pragma unroll
    for (int k = 0; k < 16; k += 2) {
        ulonglong2 w0 = w[k], w1 = w[k + 1];
        ulonglong2 v0 = v[k], v1 = v[k + 1];
        FMA2(a0, w0.x, v0.x);
        FMA2(a1, w0.y, v0.y);
        FMA2(a2, w1.x, v1.x);
        FMA2(a3, w1.y, v1.y);
    }
    return ((lo32(a0) + hi32(a0)) + (lo32(a1) + hi32(a1)))
         + ((lo32(a2) + hi32(a2)) + (lo32(a3) + hi32(a3)));
}

// dot of register row with smem vector
__device__ __forceinline__ float dot64r(const u64* __restrict__ w,
                                        const ulonglong2* __restrict__ v) {
    u64 a0 = 0ull, a1 = 0ull, a2 = 0ull, a3 = 0ull;
#pragma unroll
    for (int k = 0; k < 16; k += 2) {
        ulonglong2 v0 = v[k], v1 = v[k + 1];
        FMA2(a0, w[2*k],     v0.x);
        FMA2(a1, w[2*k + 1], v0.y);
        FMA2(a2, w[2*k + 2], v1.x);
        FMA2(a3, w[2*k + 3], v1.y);
    }
    return ((lo32(a0) + hi32(a0)) + (lo32(a1) + hi32(a1)))
         + ((lo32(a2) + hi32(a2)) + (lo32(a3) + hi32(a3)));
}

// Epilogue: lane l holds pre-activation for gate (l>>3), row w*8+(l&7).
__device__ __forceinline__ void epi(float acc, float& c,
                                    float* __restrict__ hout,
                                    int l, int rowIdx) {
    int grp = l >> 3, r8 = l & 7;
    float act = (grp == 2) ? ftanh(acc) : fsig(acc);
    float ai = __shfl_sync(0xffffffffu, act, r8);
    float af = __shfl_sync(0xffffffffu, act, r8 + 8);
    float ag = __shfl_sync(0xffffffffu, act, r8 + 16);
    float ao = __shfl_sync(0xffffffffu, act, r8 + 24);
    float cn = af * c + ai * ag;
    c = cn;
    float hv = ao * ftanh(cn);
    if (l < 8) hout[rowIdx] = hv;
    __syncthreads();
}

__global__ __launch_bounds__(256, 1)
void enas_controller_kernel(const float* __restrict__ g_emb,
                            const float* __restrict__ w_emb,
                            const float* __restrict__ w_soft,
                            const float* __restrict__ w_attn2,
                            const float* __restrict__ v_attn,
                            const float* __restrict__ w_ih0,
                            const float* __restrict__ w_hh0,
                            const float* __restrict__ b_ih0,
                            const float* __restrict__ b_hh0,
                            const float* __restrict__ w_ih1,
                            const float* __restrict__ w_hh1,
                            const float* __restrict__ b_ih1,
                            const float* __restrict__ b_hh1,
                            const int* __restrict__ seed_p,
                            float* __restrict__ out3) {
    extern __shared__ __align__(16) float S[];
    unsigned* SI = (unsigned*)&S[OF_IREG];
    const int t = threadIdx.x;
    const int w = t >> 5, l = t & 31;
    const int grp = l >> 3, r8 = l & 7;
    const int rowIdx = w * 8 + r8;
    const int R = grp * 64 + rowIdx;

    // ---- stage weights into smem ----
    {
        const float4* g0 = (const float4*)w_ih0;
        for (int idx = t; idx < 256*16; idx += 256) {
            int row = idx >> 4, col = idx & 15;
            *(float4*)&S[OF_WI0 + row*PAD + col*4] = __ldg(&g0[idx]);
        }
        const float4* ga = (const float4*)w_attn2;
        for (int idx = t; idx < 64*16; idx += 256) {
            int row = idx >> 4, col = idx & 15;
            *(float4*)&S[OF_WAT2 + row*PAD + col*4] = __ldg(&ga[idx]);
        }
        const float4* gs = (const float4*)w_soft;
        if (t < NB*16) *(float4*)&S[OF_WSOFT + t*4] = __ldg(&gs[t]);
        const float4* ge = (const float4*)w_emb;
        if (t >= 32 && t < 32 + NB*16) *(float4*)&S[OF_WEMB + (t-32)*4] = __ldg(&ge[t-32]);
        if (t >= 128 && t < 144) *(float4*)&S[OF_GEMB + (t-128)*4] = __ldg(&((const float4*)g_emb)[t-128]);
        if (t >= 160 && t < 160 + HID) {
            S[OF_VATTN + t - 160] = __ldg(&v_attn[t - 160]);
            S[OF_H0A + t - 160] = 0.f;
            S[OF_H1A + t - 160] = 0.f;
        }
    }

    // ---- register weights: wh0, wh1, wi1 rows for gate row R ----
    u64 wh0[32], wh1[32], wi1[32];
    {
        const ulonglong2* p0 = (const ulonglong2*)(w_hh0 + R*HID);
        const ulonglong2* p1 = (const ulonglong2*)(w_hh1 + R*HID);
        const ulonglong2* p2 = (const ulonglong2*)(w_ih1 + R*HID);
#pragma unroll
        for (int k = 0; k < 16; k++) {
            ulonglong2 v0 = __ldg(&p0[k]);
            ulonglong2 v1 = __ldg(&p1[k]);
            ulonglong2 v2 = __ldg(&p2[k]);
            wh0[2*k] = v0.x; wh0[2*k + 1] = v0.y;
            wh1[2*k] = v1.x; wh1[2*k + 1] = v1.y;
            wi1[2*k] = v2.x; wi1[2*k + 1] = v2.y;
        }
    }
    const float b0R = __ldg(&b_ih0[R]) + __ldg(&b_hh0[R]);
    const float b1R = __ldg(&b_ih1[R]) + __ldg(&b_hh1[R]);

    // ---- RNG: serial key chain, then keys + all gumbels in parallel ----
    if (t == 0) {
        unsigned k0 = 0u, k1 = (unsigned)seed_p[0];
        for (int lid = 0; lid < N_LAYERS; lid++) {
            SI[IO_LKEY + 2*lid]     = k0;
            SI[IO_LKEY + 2*lid + 1] = k1;
            unsigned a0, a1;
            tf2x32(k0, k1, 0u, 0u, a0, a1);
            k0 = a0; k1 = a1;
        }
    }
    __syncthreads();
    if (t < 24) {
        int lid = t >> 1, which = t & 1;
        unsigned o0, o1;
        tf2x32(SI[IO_LKEY + 2*lid], SI[IO_LKEY + 2*lid + 1], 0u, (unsigned)(1 + which), o0, o1);
        int base = which ? IO_KS : IO_KB;
        SI[base + 2*lid] = o0; SI[base + 2*lid + 1] = o1;
    }
    // ---- P table: P[b][R] = bsum0[R] + w_ih0[R,:] . vec_b ----
    {
        const ulonglong2* wrow = (const ulonglong2*)&S[OF_WI0 + R*PAD];
#pragma unroll
        for (int b = 0; b < 7; b++) {
            const ulonglong2* vec = (const ulonglong2*)
                ((b < 6) ? &S[OF_WEMB + b*HID] : &S[OF_GEMB]);
            S[OF_P + b*256 + R] = b0R + dot64p(wrow, vec);
        }
    }
    __syncthreads();
    if (t < 72) {
        int lid = t / NB, j = t % NB;
        S[OF_GUMB + lid*NB + j] =
            gumbel_from_bits(rbits32(SI[IO_KB + 2*lid], SI[IO_KB + 2*lid + 1], j));
    } else if (t < 72 + 132) {
        int f = t - 72;
        int lid = 1;
        while (f >= lid*(lid+1)) lid++;
        int j = f - lid*(lid-1);
        S[OF_GUMS + f] =
            gumbel_from_bits(rbits32(SI[IO_KS + 2*lid], SI[IO_KS + 2*lid + 1], j));
    }
    __syncthreads();

    float c0 = 0.f, c1 = 0.f;

#pragma unroll 1
    for (int lid = 0; lid < N_LAYERS; ++lid) {
        // ===== phase 1: call1-cell0 (reads H0A -> H0B); also hoist wh1.H1A =====
        float sb1;  // wh1 . h1_prev for phase 2 (input ready since last layer)
        {
            float acc = (lid < 2)
                ? S[OF_P + 6*256 + R]
                : b0R + dot64p((const ulonglong2*)&S[OF_WI0 + R*PAD],
                               (const ulonglong2*)&S[OF_XS]);
            acc += dot64r(wh0, (const ulonglong2*)&S[OF_H0A]);
            sb1 = dot64r(wh1, (const ulonglong2*)&S[OF_H1A]);
            epi(acc, c0, &S[OF_H0B], l, rowIdx);
        }
        // ===== phase 2: call1-cell1 (only wi1.H0B remains) =====
        {
            float sa = dot64r(wi1, (const ulonglong2*)&S[OF_H0B]);
            float acc = b1R + (sa + sb1);   // same order as b1R + dot64r2(...)
            epi(acc, c1, &S[OF_H1B], l, rowIdx);
        }
        // ===== phase 3+4 fused: warps 0-1 logits (verbatim R6) while all
        //       warps run the phase-4 dots; one mid-barrier; argmax+epi =====
        float sb1b;  // wh1 . H1B for phase 5
        {
            if (t < 64) {
                int j = t >> 3, k0 = t & 7;
                int jc = (j < NB) ? j : 0;
                const float4* wv = (const float4*)&S[OF_WSOFT + jc*HID + k0*8];
                const float4* hv = (const float4*)&S[OF_H1B + k0*8];
                float4 wa = wv[0], wb = wv[1];
                float4 ha = hv[0], hb = hv[1];
                float s = wa.x*ha.x + wa.y*ha.y + wa.z*ha.z + wa.w*ha.w
                        + wb.x*hb.x + wb.y*hb.y + wb.z*hb.z + wb.w*hb.w;
                s += __shfl_down_sync(0xffffffffu, s, 4, 8);
                s += __shfl_down_sync(0xffffffffu, s, 2, 8);
                s += __shfl_down_sync(0xffffffffu, s, 1, 8);
                if (k0 == 0 && j < NB) S[OF_LOGS + lid*8 + j] = s;
            }
            float pre4 = dot64r(wh0, (const ulonglong2*)&S[OF_H0B]);
            sb1b = dot64r(wh1, (const ulonglong2*)&S[OF_H1B]);
            __syncthreads();

            float bz = S[OF_LOGS + lid*8] + S[OF_GUMB + lid*NB];
            int best = 0;
#pragma unroll
            for (int j = 1; j < NB; j++) {
                float z = S[OF_LOGS + lid*8 + j] + S[OF_GUMB + lid*NB + j];
                if (z > bz) { bz = z; best = j; }
            }
            float acc = S[OF_P + best*256 + R] + pre4;
            epi(acc, c0, &S[OF_H0A], l, rowIdx);
        }
        // ===== phase 5: call2-cell1 (only wi1.H0A remains) =====
        {
            float sa = dot64r(wi1, (const ulonglong2*)&S[OF_H0A]);
            float acc = b1R + (sa + sb1b);
            epi(acc, c1, &S[OF_H1A], l, rowIdx);
        }
        // ===== phase 6: anchor (w2out = wat2 @ H1A) =====
        if (t < HID) {
            float v = dot64p((const ulonglong2*)&S[OF_WAT2 + t*PAD],
                             (const ulonglong2*)&S[OF_H1A]);
            S[OF_W2OUT + t] = v;
            S[OF_AW1 + lid*HID + t] = v;
            S[OF_ANCH + lid*HID + t] = S[OF_H1A + t];
        }
        __syncthreads();

        if (lid > 0) {
            // ===== phase 7: attention q + skip decisions (16 thr/row) =====
            if (t < 192) {
                int r = t >> 4, k0 = t & 15;
                int rc = (r < lid) ? r : 0;
                float s = 0.f;
#pragma unroll
                for (int k = 0; k < 4; k++) {
                    int j = k0 + 16*k;
                    s += ftanh(S[OF_AW1 + rc*HID + j] + S[OF_W2OUT + j]) * S[OF_VATTN + j];
                }
                s += __shfl_down_sync(0xffffffffu, s, 8, 16);
                s += __shfl_down_sync(0xffffffffu, s, 4, 16);
                s += __shfl_down_sync(0xffffffffu, s, 2, 16);
                s += __shfl_down_sync(0xffffffffu, s, 1, 16);
                if (k0 == 0 && r < lid) {
                    S[OF_QVS + lid*16 + r] = s;
                    // decision with the exact same ops as before (bitwise)
                    float l0 = 1.5f * ftanh(s);
                    float g0 = S[OF_GUMS + lid*(lid-1) + 2*r];
                    float g1 = S[OF_GUMS + lid*(lid-1) + 2*r + 1];
                    S[OF_SKF + r] = ((-l0) + g1 > l0 + g0) ? 1.0f : 0.0f;
                }
            }
            __syncthreads();

            // ===== phase 8: xs from precomputed skip flags (LDS+FMA only) =====
            if (t < HID) {
                float scf = 0.f;
                float acc = 0.f;
                for (int i = 0; i < lid; i++) {
                    float f = S[OF_SKF + i];
                    scf += f;
                    acc += f * S[OF_ANCH + i*HID + t];
                }
                S[OF_XS + t] = __fdividef(acc, 1.0f + scf);
            }
            __syncthreads();
        }
    }

    // ===== deferred stats (once) =====
    if (t < 12) {
        float lv[NB];
#pragma unroll
        for (int j = 0; j < NB; j++) lv[j] = S[OF_LOGS + t*8 + j];
        float m = lv[0];
#pragma unroll
        for (int j = 1; j < NB; j++) m = fmaxf(m, lv[j]);
        float s = 0.f;
#pragma unroll
        for (int j = 0; j < NB; j++) s += __expf(lv[j] - m);
        float lse = __logf(s);
        int best = 0;
        float bz = lv[0] + S[OF_GUMB + t*NB];
#pragma unroll
        for (int j = 1; j < NB; j++) {
            float z = lv[j] + S[OF_GUMB + t*NB + j];
            if (z > bz) { bz = z; best = j; }
        }
        S[OF_BLP + t] = (lv[best] - m) - lse;
        float ent = 0.f;
#pragma unroll
        for (int j = 0; j < NB; j++) {
            float lp = (lv[j] - m) - lse;
            ent -= __expf(lp) * lp;
        }
        S[OF_BENT + t] = ent;
    } else if (t >= 64 && t < 64 + 66) {
        int f = t - 64;                    // slot = lid*(lid-1)/2 + r
        int lid = 1;
        while (f >= (lid*(lid+1)) >> 1) lid++;
        int r = f - ((lid*(lid-1)) >> 1);
        float q = S[OF_QVS + lid*16 + r];
        float l0 = 1.5f * ftanh(q);        // same ops as phase-7 decision
        float l1 = -l0;
        float g0 = S[OF_GUMS + lid*(lid-1) + 2*r];
        float g1 = S[OF_GUMS + lid*(lid-1) + 2*r + 1];
        float m = fmaxf(l0, l1);
        float lsr = __logf(__expf(l0 - m) + __expf(l1 - m));
        float lp0 = (l0 - m) - lsr;
        float lp1 = (l1 - m) - lsr;
        S[OF_SLP + f]  = (l1 + g1 > l0 + g0) ? lp1 : lp0;
        S[OF_SENT + f] = -(__expf(lp0)*lp0 + __expf(lp1)*lp1);
        float s0 = __fdividef(1.0f, 1.0f + __expf(-l0));
        float s1 = __fdividef(1.0f, 1.0f + __expf(-l1));
        S[OF_SKL + f] = s0 * __logf(__fdividef(s0, 0.8f))
                      + s1 * __logf(__fdividef(s1, 0.8f));
    }
    __syncthreads();

    if (t < 32) {
        float s1 = 0.f, s2 = 0.f, s3 = 0.f;
        for (int i = t; i < 12; i += 32) { s1 += S[OF_BLP + i]; s2 += S[OF_BENT + i]; }
        for (int i = t; i < 66; i += 32) {
            s1 += S[OF_SLP + i]; s2 += S[OF_SENT + i]; s3 += S[OF_SKL + i];
        }
#pragma unroll
        for (int off = 16; off > 0; off >>= 1) {
            s1 += __shfl_down_sync(0xffffffffu, s1, off);
            s2 += __shfl_down_sync(0xffffffffu, s2, off);
            s3 += __shfl_down_sync(0xffffffffu, s3, off);
        }
        if (t == 0) {
            out3[0] = s1;
            out3[1] = s2;
            out3[2] = s3;
        }
    }
}

extern "C" void kernel_launch(void* const* d_in, const int* in_sizes, int n_in,
                              void* d_out, int out_size) {
    const float* g_emb   = (const float*)d_in[0];
    const float* w_emb   = (const float*)d_in[1];
    const float* w_soft  = (const float*)d_in[2];
    const float* w_attn2 = (const float*)d_in[3];
    const float* v_attn  = (const float*)d_in[4];
    const float* w_ih0   = (const float*)d_in[5];
    const float* w_hh0   = (const float*)d_in[6];
    const float* b_ih0   = (const float*)d_in[7];
    const float* b_hh0   = (const float*)d_in[8];
    const float* w_ih1   = (const float*)d_in[9];
    const float* w_hh1   = (const float*)d_in[10];
    const float* b_ih1   = (const float*)d_in[11];
    const float* b_hh1   = (const float*)d_in[12];
    const int*   seed    = (const int*)d_in[13];

    cudaFuncSetAttribute(enas_controller_kernel,
                         cudaFuncAttributeMaxDynamicSharedMemorySize, SMEM_BYTES);
    enas_controller_kernel<<<1, 256, SMEM_BYTES>>>(
        g_emb, w_emb, w_soft, w_attn2, v_attn,
        w_ih0, w_hh0, b_ih0, b_hh0,
        w_ih1, w_hh1, b_ih1, b_hh1,
        seed, (float*)d_out);
}